// round 3
// baseline (speedup 1.0000x reference)
#include <cuda_runtime.h>
#include <cstdint>

#define C 128
#define NMAX 200000
#define EPSF 1e-5f

// ---------------- scratch (static device allocations only) ----------------
__device__ __align__(16) float g_x[NMAX * C];    // voxel features (also xsum)
__device__ __align__(16) float g_t1[NMAX * C];
__device__ __align__(16) float g_t2[NMAX * C];
__device__ __align__(16) float g_cnt[NMAX];
__device__ __align__(16) float g_stats[2 * C];   // per-channel sum, sumsq
__device__ __align__(16) float g_ss[2 * C];      // per-channel scale, shift

// ---------------- f32x2 helpers (sm_100+) ----------------
typedef unsigned long long u64;
__device__ __forceinline__ u64 dup2(float x) {
    u64 r; asm("mov.b64 %0, {%1, %1};" : "=l"(r) : "f"(x)); return r;
}
__device__ __forceinline__ void ffma2(u64& d, u64 a, u64 b) {
    asm("fma.rn.f32x2 %0, %1, %2, %0;" : "+l"(d) : "l"(a), "l"(b));
}
__device__ __forceinline__ float2 unpack2(u64 v) {
    float2 r; asm("mov.b64 {%0, %1}, %2;" : "=f"(r.x), "=f"(r.y) : "l"(v)); return r;
}

// ---------------- zero scratch ----------------
__global__ void zero_kernel(float* __restrict__ x, float* __restrict__ cnt, int M) {
    int stride = gridDim.x * blockDim.x;
    int tot = M * C;
    for (int i = blockIdx.x * blockDim.x + threadIdx.x; i < tot; i += stride) x[i] = 0.f;
    for (int i = blockIdx.x * blockDim.x + threadIdx.x; i < M;   i += stride) cnt[i] = 0.f;
}

__global__ void zero_stats_kernel(float* __restrict__ s) {
    if (threadIdx.x < 2 * C) s[threadIdx.x] = 0.f;
}

// ---------------- encoder: Linear(14->128) + LayerNorm + ReLU + segment-sum scatter ----------------
__global__ __launch_bounds__(256) void encoder_kernel(
    const float* __restrict__ gp, const float* __restrict__ w_enc,
    const float* __restrict__ b_enc, const float* __restrict__ ln_g,
    const float* __restrict__ ln_b, const int* __restrict__ inv,
    float* __restrict__ xsum, float* __restrict__ cnt, int N)
{
    __shared__ __align__(16) float shW[14 * C];
    for (int i = threadIdx.x; i < 14 * C; i += blockDim.x) shW[i] = w_enc[i];
    __syncthreads();
    const int lane = threadIdx.x & 31;
    const int gw = (blockIdx.x * blockDim.x + threadIdx.x) >> 5;
    const int nw = (gridDim.x * blockDim.x) >> 5;
    for (int p = gw; p < N; p += nw) {
        float gv[14];
#pragma unroll
        for (int k = 0; k < 14; ++k) gv[k] = __ldg(&gp[p * 14 + k]);
        float f[4];
#pragma unroll
        for (int j = 0; j < 4; ++j) {
            int c = lane + 32 * j;
            float acc = __ldg(&b_enc[c]);
#pragma unroll
            for (int k = 0; k < 14; ++k) acc = fmaf(gv[k], shW[k * C + c], acc);
            f[j] = acc;
        }
        float s = f[0] + f[1] + f[2] + f[3];
        float s2 = f[0]*f[0] + f[1]*f[1] + f[2]*f[2] + f[3]*f[3];
#pragma unroll
        for (int m = 16; m; m >>= 1) {
            s  += __shfl_xor_sync(0xffffffffu, s,  m);
            s2 += __shfl_xor_sync(0xffffffffu, s2, m);
        }
        float mean = s * (1.f / C);
        float var = s2 * (1.f / C) - mean * mean;
        float rs = rsqrtf(var + EPSF);
        int v = inv[p];
        float* base = xsum + (size_t)v * C;
#pragma unroll
        for (int j = 0; j < 4; ++j) {
            int c = lane + 32 * j;
            float y = fmaf((f[j] - mean) * rs, __ldg(&ln_g[c]), __ldg(&ln_b[c]));
            y = fmaxf(y, 0.f);
            atomicAdd(&base[c], y);
        }
        if (lane == 0) atomicAdd(&cnt[v], 1.f);
    }
}

// ---------------- segment mean: x /= cnt ----------------
__global__ void divide_kernel(float* __restrict__ x, const float* __restrict__ cnt, int total) {
    int stride = gridDim.x * blockDim.x;
    for (int i = blockIdx.x * blockDim.x + threadIdx.x; i < total; i += stride)
        x[i] = x[i] / cnt[i >> 7];
}

// ---------------- submanifold conv: out[v] = sum_o mask*x[nbr[v,o]] @ W[o] ----------------
// 128 threads: 4 warps x 16 voxels. Each warp covers all 128 out-channels
// as 2 f32x2 pairs per lane (c = 4*lane + {0..3}).
__global__ __launch_bounds__(128) void conv_kernel(
    const float* __restrict__ xin, float* __restrict__ out,
    const float* __restrict__ Wg, const int* __restrict__ nbr_idx,
    const float* __restrict__ nbr_mask, int M)
{
    extern __shared__ __align__(16) float sh[];
    float* shW = sh;            // 128*128 floats (64 KB)
    float* shA = sh + C * C;    // 64*128  floats (32 KB)
    const int lane = threadIdx.x & 31;
    const int warp = threadIdx.x >> 5;
    const int vbase = blockIdx.x * 64 + warp * 16;

    u64 acc[16][2];
#pragma unroll
    for (int t = 0; t < 16; ++t) { acc[t][0] = 0ull; acc[t][1] = 0ull; }

#pragma unroll 1
    for (int o = 0; o < 27; ++o) {
        __syncthreads();  // previous compute done before restaging
        // stage W[o] (row-major [k][c]) into smem
        {
            const float4* Wg4 = (const float4*)(Wg + o * C * C);
            float4* shW4 = (float4*)shW;
#pragma unroll
            for (int i = 0; i < 32; ++i)
                shW4[threadIdx.x + i * 128] = Wg4[threadIdx.x + i * 128];
        }
        // gather masked neighbor rows (each warp fills its own 16 rows)
#pragma unroll
        for (int t = 0; t < 16; ++t) {
            int v = vbase + t;
            float4 val = make_float4(0.f, 0.f, 0.f, 0.f);
            if (v < M) {
                float m = __ldg(&nbr_mask[v * 27 + o]);
                if (m != 0.f) {
                    int nb = __ldg(&nbr_idx[v * 27 + o]);
                    val = ((const float4*)(xin + (size_t)nb * C))[lane];
                }
            }
            ((float4*)(shA + (warp * 16 + t) * C))[lane] = val;
        }
        __syncthreads();
        // compute: acc[t] += A[t][k..k+3] * W[k..k+3][4*lane..4*lane+3]
        const ulonglong2* shWp = (const ulonglong2*)shW;
        const float4* shAp = (const float4*)(shA + (warp * 16) * C);
#pragma unroll 1
        for (int k = 0; k < C; k += 4) {
            ulonglong2 w0 = shWp[(k + 0) * 32 + lane];
            ulonglong2 w1 = shWp[(k + 1) * 32 + lane];
            ulonglong2 w2 = shWp[(k + 2) * 32 + lane];
            ulonglong2 w3 = shWp[(k + 3) * 32 + lane];
#pragma unroll
            for (int t = 0; t < 16; ++t) {
                float4 a = shAp[t * 32 + (k >> 2)];
                u64 ax = dup2(a.x), ay = dup2(a.y), az = dup2(a.z), aw = dup2(a.w);
                ffma2(acc[t][0], ax, w0.x); ffma2(acc[t][1], ax, w0.y);
                ffma2(acc[t][0], ay, w1.x); ffma2(acc[t][1], ay, w1.y);
                ffma2(acc[t][0], az, w2.x); ffma2(acc[t][1], az, w2.y);
                ffma2(acc[t][0], aw, w3.x); ffma2(acc[t][1], aw, w3.y);
            }
        }
    }
#pragma unroll
    for (int t = 0; t < 16; ++t) {
        int v = vbase + t;
        if (v < M) {
            float2 p0 = unpack2(acc[t][0]);
            float2 p1 = unpack2(acc[t][1]);
            ((float4*)(out + (size_t)v * C))[lane] = make_float4(p0.x, p0.y, p1.x, p1.y);
        }
    }
}

// ---------------- BN: per-channel sum / sumsq ----------------
__global__ __launch_bounds__(128) void bnstats_kernel(
    const float* __restrict__ y, float* __restrict__ stats, int M)
{
    int c = threadIdx.x;
    float s = 0.f, s2 = 0.f;
    for (int r = blockIdx.x; r < M; r += gridDim.x) {
        float v = y[(size_t)r * C + c];
        s += v; s2 += v * v;
    }
    atomicAdd(&stats[c], s);
    atomicAdd(&stats[C + c], s2);
}

__global__ void bnfinalize_kernel(
    const float* __restrict__ stats, const float* __restrict__ g,
    const float* __restrict__ b, float* __restrict__ ss, int M)
{
    int c = threadIdx.x;
    if (c < C) {
        float invM = 1.f / (float)M;
        float mean = stats[c] * invM;
        float var = stats[C + c] * invM - mean * mean;
        float sc = g[c] * rsqrtf(var + EPSF);
        ss[c] = sc;
        ss[C + c] = b[c] - mean * sc;
    }
}

// out = relu(y*scale + shift [+ resid])
__global__ void bnapply_kernel(
    const float* __restrict__ yin, const float* __restrict__ ss,
    const float* __restrict__ resid, float* __restrict__ out, int total)
{
    int stride = gridDim.x * blockDim.x;
    for (int i = blockIdx.x * blockDim.x + threadIdx.x; i < total; i += stride) {
        int c = i & (C - 1);
        float v = fmaf(yin[i], ss[c], ss[C + c]);
        if (resid) v += resid[i];
        out[i] = fmaxf(v, 0.f);
    }
}

// ---------------- head: gather + Linear(128->64)+ReLU + Linear(64->14) + residual ----------------
__global__ __launch_bounds__(256) void head_kernel(
    const float* __restrict__ x, const int* __restrict__ inv,
    const float* __restrict__ gp, const float* __restrict__ w1,
    const float* __restrict__ b1, const float* __restrict__ w2,
    const float* __restrict__ b2, float* __restrict__ out, int N)
{
    __shared__ __align__(16) float shW1[C * 64];
    __shared__ __align__(16) float shW2[64 * 14];
    __shared__ __align__(16) float shB1[64];
    __shared__ __align__(16) float shB2[16];
    __shared__ __align__(16) float shPF[8][C];
    __shared__ __align__(16) float shH[8][64];
    for (int i = threadIdx.x; i < C * 64; i += 256) shW1[i] = w1[i];
    for (int i = threadIdx.x; i < 64 * 14; i += 256) shW2[i] = w2[i];
    if (threadIdx.x < 64) shB1[threadIdx.x] = b1[threadIdx.x];
    if (threadIdx.x < 14) shB2[threadIdx.x] = b2[threadIdx.x];
    __syncthreads();
    const int lane = threadIdx.x & 31;
    const int w = threadIdx.x >> 5;
    const int gw = (blockIdx.x * 256 + threadIdx.x) >> 5;
    const int nw = gridDim.x * 8;
    for (int p = gw; p < N; p += nw) {
        int v = inv[p];
        ((float4*)shPF[w])[lane] = ((const float4*)(x + (size_t)v * C))[lane];
        __syncwarp();
        float h0 = shB1[lane], h1 = shB1[lane + 32];
#pragma unroll 8
        for (int k = 0; k < C; ++k) {
            float a = shPF[w][k];
            h0 = fmaf(a, shW1[k * 64 + lane], h0);
            h1 = fmaf(a, shW1[k * 64 + lane + 32], h1);
        }
        h0 = fmaxf(h0, 0.f); h1 = fmaxf(h1, 0.f);
        shH[w][lane] = h0; shH[w][lane + 32] = h1;
        __syncwarp();
        if (lane < 14) {
            float d = shB2[lane];
#pragma unroll
            for (int j = 0; j < 64; ++j) d = fmaf(shH[w][j], shW2[j * 14 + lane], d);
            out[p * 14 + lane] = gp[p * 14 + lane] + d;
        }
        __syncwarp();
    }
}

// ---------------- launch ----------------
extern "C" void kernel_launch(void* const* d_in, const int* in_sizes, int n_in,
                              void* d_out, int out_size)
{
    const float* gp       = (const float*)d_in[0];
    const float* w_enc    = (const float*)d_in[1];
    const float* b_enc    = (const float*)d_in[2];
    const float* ln_g     = (const float*)d_in[3];
    const float* ln_b     = (const float*)d_in[4];
    const float* conv_w   = (const float*)d_in[5];
    const float* bn_g     = (const float*)d_in[6];
    const float* bn_b     = (const float*)d_in[7];
    const float* w1       = (const float*)d_in[8];
    const float* b1       = (const float*)d_in[9];
    const float* w2       = (const float*)d_in[10];
    const float* b2       = (const float*)d_in[11];
    const float* nbr_mask = (const float*)d_in[12];
    const int*   inv_idx  = (const int*)d_in[13];
    const int*   nbr_idx  = (const int*)d_in[14];
    float* out = (float*)d_out;

    const int N = in_sizes[0] / 14;
    const int M = in_sizes[12] / 27;

    float *px, *pt1, *pt2, *pcnt, *pstats, *pss;
    cudaGetSymbolAddress((void**)&px,     g_x);
    cudaGetSymbolAddress((void**)&pt1,    g_t1);
    cudaGetSymbolAddress((void**)&pt2,    g_t2);
    cudaGetSymbolAddress((void**)&pcnt,   g_cnt);
    cudaGetSymbolAddress((void**)&pstats, g_stats);
    cudaGetSymbolAddress((void**)&pss,    g_ss);

    const int convSmem = (C * C + 64 * C) * (int)sizeof(float);  // 96 KB
    cudaFuncSetAttribute(conv_kernel, cudaFuncAttributeMaxDynamicSharedMemorySize, convSmem);

    // encoder + scatter mean
    zero_kernel<<<1184, 256>>>(px, pcnt, M);
    encoder_kernel<<<1024, 256>>>(gp, w_enc, b_enc, ln_g, ln_b, inv_idx, px, pcnt, N);
    divide_kernel<<<1184, 256>>>(px, pcnt, M * C);

    const int convGrid = (M + 63) / 64;
    // stage 0: conv0(x)->t1, bn+relu in place
    conv_kernel<<<convGrid, 128, convSmem>>>(px, pt1, conv_w + 0 * 27 * C * C, nbr_idx, nbr_mask, M);
    zero_stats_kernel<<<1, 256>>>(pstats);
    bnstats_kernel<<<1024, 128>>>(pt1, pstats, M);
    bnfinalize_kernel<<<1, 128>>>(pstats, bn_g + 0 * C, bn_b + 0 * C, pss, M);
    bnapply_kernel<<<1184, 256>>>(pt1, pss, nullptr, pt1, M * C);
    // stage 1: conv1(t1)->t2, bn + residual(x) + relu -> x
    conv_kernel<<<convGrid, 128, convSmem>>>(pt1, pt2, conv_w + 1 * 27 * C * C, nbr_idx, nbr_mask, M);
    zero_stats_kernel<<<1, 256>>>(pstats);
    bnstats_kernel<<<1024, 128>>>(pt2, pstats, M);
    bnfinalize_kernel<<<1, 128>>>(pstats, bn_g + 1 * C, bn_b + 1 * C, pss, M);
    bnapply_kernel<<<1184, 256>>>(pt2, pss, px, px, M * C);
    // stage 2
    conv_kernel<<<convGrid, 128, convSmem>>>(px, pt1, conv_w + 2 * 27 * C * C, nbr_idx, nbr_mask, M);
    zero_stats_kernel<<<1, 256>>>(pstats);
    bnstats_kernel<<<1024, 128>>>(pt1, pstats, M);
    bnfinalize_kernel<<<1, 128>>>(pstats, bn_g + 2 * C, bn_b + 2 * C, pss, M);
    bnapply_kernel<<<1184, 256>>>(pt1, pss, nullptr, pt1, M * C);
    // stage 3
    conv_kernel<<<convGrid, 128, convSmem>>>(pt1, pt2, conv_w + 3 * 27 * C * C, nbr_idx, nbr_mask, M);
    zero_stats_kernel<<<1, 256>>>(pstats);
    bnstats_kernel<<<1024, 128>>>(pt2, pstats, M);
    bnfinalize_kernel<<<1, 128>>>(pstats, bn_g + 3 * C, bn_b + 3 * C, pss, M);
    bnapply_kernel<<<1184, 256>>>(pt2, pss, px, px, M * C);

    // head
    head_kernel<<<1024, 256>>>(px, inv_idx, gp, w1, b1, w2, b2, out, N);
}

// round 11
// speedup vs baseline: 2.7529x; 2.7529x over previous
#include <cuda_runtime.h>
#include <cuda_bf16.h>
#include <cstdint>

#define C 128
#define NMAX 200000
#define EPSF 1e-5f

// ---------------- scratch ----------------
__device__ __align__(16) float        g_x[NMAX * C];     // fp32 voxel features (xsum -> x)
__device__ __align__(16) float        g_y[NMAX * C];     // fp32 conv output
__device__ __align__(16) unsigned int g_p[NMAX * C];     // packed (bf16hi<<16)|bf16lo conv input
__device__ __align__(16) unsigned int g_wfrag[4 * 27 * C * C]; // per-lane HMMA B fragments
__device__ __align__(16) float        g_cnt[NMAX];
__device__ __align__(16) float        g_stats[2 * C];
__device__ __align__(16) float        g_ss[2 * C];

// ---------------- helpers ----------------
__device__ __forceinline__ unsigned int packhl(float x) {
    __nv_bfloat16 h = __float2bfloat16(x);
    float hf = __bfloat162float(h);
    __nv_bfloat16 l = __float2bfloat16(x - hf);
    return ((unsigned int)__bfloat16_as_ushort(h) << 16) | (unsigned int)__bfloat16_as_ushort(l);
}
__device__ __forceinline__ void split16(float x, unsigned int& hi, unsigned int& lo) {
    __nv_bfloat16 h = __float2bfloat16(x);
    float hf = __bfloat162float(h);
    __nv_bfloat16 l = __float2bfloat16(x - hf);
    hi = (unsigned int)__bfloat16_as_ushort(h);
    lo = (unsigned int)__bfloat16_as_ushort(l);
}
__device__ __forceinline__ void mma_bf16(float* c, uint32_t a0, uint32_t a1, uint32_t a2, uint32_t a3,
                                         uint32_t b0, uint32_t b1) {
    asm volatile(
        "mma.sync.aligned.m16n8k16.row.col.f32.bf16.bf16.f32 "
        "{%0,%1,%2,%3}, {%4,%5,%6,%7}, {%8,%9}, {%0,%1,%2,%3};"
        : "+f"(c[0]), "+f"(c[1]), "+f"(c[2]), "+f"(c[3])
        : "r"(a0), "r"(a1), "r"(a2), "r"(a3), "r"(b0), "r"(b1));
}

// ---------------- zero scratch ----------------
__global__ void zero_kernel(float* __restrict__ x, float* __restrict__ cnt, int M) {
    int stride = gridDim.x * blockDim.x;
    int tot = M * C;
    for (int i = blockIdx.x * blockDim.x + threadIdx.x; i < tot; i += stride) x[i] = 0.f;
    for (int i = blockIdx.x * blockDim.x + threadIdx.x; i < M;   i += stride) cnt[i] = 0.f;
}
__global__ void zero_stats_kernel(float* __restrict__ s) {
    if (threadIdx.x < 2 * C) s[threadIdx.x] = 0.f;
}

// ---------------- weight -> HMMA B fragments ----------------
// wfrag[s][o][ks][nt][lane] = uint4 {b0hi, b1hi, b0lo, b1lo}
// B element (k, n): b0 covers k = ks*16 + (lane%4)*2 + {0,1}, n = nt*8 + lane/4; b1 covers k+8.
__global__ void wfrag_kernel(const float* __restrict__ w, uint4* __restrict__ out, int total4) {
    for (int i = blockIdx.x * blockDim.x + threadIdx.x; i < total4; i += gridDim.x * blockDim.x) {
        int lane = i & 31;
        int nt = (i >> 5) & 15;
        int ks = (i >> 9) & 7;
        int o = (i >> 12) % 27;
        int s = i / 110592;
        int k0 = ks * 16 + (lane & 3) * 2;
        int n = nt * 8 + (lane >> 2);
        const float* src = w + ((size_t)(s * 27 + o) << 14);
        unsigned int h00, l00, h01, l01, h10, l10, h11, l11;
        split16(src[(k0 + 0) * 128 + n], h00, l00);
        split16(src[(k0 + 1) * 128 + n], h01, l01);
        split16(src[(k0 + 8) * 128 + n], h10, l10);
        split16(src[(k0 + 9) * 128 + n], h11, l11);
        out[i] = make_uint4(h00 | (h01 << 16), h10 | (h11 << 16),
                            l00 | (l01 << 16), l10 | (l11 << 16));
    }
}

// ---------------- encoder: Linear(14->128)+LN+ReLU + segment-sum scatter ----------------
__global__ __launch_bounds__(256) void encoder_kernel(
    const float* __restrict__ gp, const float* __restrict__ w_enc,
    const float* __restrict__ b_enc, const float* __restrict__ ln_g,
    const float* __restrict__ ln_b, const int* __restrict__ inv,
    float* __restrict__ xsum, float* __restrict__ cnt, int N)
{
    __shared__ __align__(16) float shW[14 * C];
    for (int i = threadIdx.x; i < 14 * C; i += blockDim.x) shW[i] = w_enc[i];
    __syncthreads();
    const int lane = threadIdx.x & 31;
    const int gw = (blockIdx.x * blockDim.x + threadIdx.x) >> 5;
    const int nw = (gridDim.x * blockDim.x) >> 5;
    for (int p = gw; p < N; p += nw) {
        float gv[14];
#pragma unroll
        for (int k = 0; k < 14; ++k) gv[k] = __ldg(&gp[p * 14 + k]);
        float f[4];
#pragma unroll
        for (int j = 0; j < 4; ++j) {
            int c = lane + 32 * j;
            float acc = __ldg(&b_enc[c]);
#pragma unroll
            for (int k = 0; k < 14; ++k) acc = fmaf(gv[k], shW[k * C + c], acc);
            f[j] = acc;
        }
        float s = f[0] + f[1] + f[2] + f[3];
        float s2 = f[0]*f[0] + f[1]*f[1] + f[2]*f[2] + f[3]*f[3];
#pragma unroll
        for (int m = 16; m; m >>= 1) {
            s  += __shfl_xor_sync(0xffffffffu, s,  m);
            s2 += __shfl_xor_sync(0xffffffffu, s2, m);
        }
        float mean = s * (1.f / C);
        float var = s2 * (1.f / C) - mean * mean;
        float rs = rsqrtf(var + EPSF);
        int v = inv[p];
        float* base = xsum + (size_t)v * C;
#pragma unroll
        for (int j = 0; j < 4; ++j) {
            int c = lane + 32 * j;
            float yv = fmaf((f[j] - mean) * rs, __ldg(&ln_g[c]), __ldg(&ln_b[c]));
            yv = fmaxf(yv, 0.f);
            atomicAdd(&base[c], yv);
        }
        if (lane == 0) atomicAdd(&cnt[v], 1.f);
    }
}

// ---------------- segment mean + pack ----------------
__global__ void divide_pack_kernel(float* __restrict__ x, const float* __restrict__ cnt,
                                   unsigned int* __restrict__ xp, int total) {
    int stride = gridDim.x * blockDim.x;
    for (int i = blockIdx.x * blockDim.x + threadIdx.x; i < total; i += stride) {
        float v = x[i] / cnt[i >> 7];
        x[i] = v;
        xp[i] = packhl(v);
    }
}

// ---------------- HMMA submanifold conv ----------------
// CTA: 256 voxels, 512 threads (16 warps). Warp w owns rows w*16..w*16+15.
// Per offset o: stage W-frags (64KB) to smem, gather A rows from gmem (packed hi|lo),
// 3-pass mma: Ahi*Whi + Ahi*Wlo + Alo*Whi.
#define CONV_SMEM (65536 + 128)
__global__ __launch_bounds__(512, 1) void conv_mma_kernel(
    const unsigned int* __restrict__ xp, float* __restrict__ y,
    const uint4* __restrict__ wfrag,        // [27][8][16][32] uint4
    const int* __restrict__ nbr_idx, const float* __restrict__ nbr_mask, int M)
{
    extern __shared__ __align__(16) char smem[];
    uint4* shW = (uint4*)smem;              // 4096 uint4
    int* shFlag = (int*)(smem + 65536);     // 16 warp flags

    const int tid = threadIdx.x;
    const int wid = tid >> 5;
    const int lane = tid & 31;
    const int qr = lane >> 2;               // row-in-strip 0..7
    const int col0 = (lane & 3) * 2;

    const int vbase = blockIdx.x * 256 + wid * 16;
    const int v0 = vbase + qr;
    const int v1 = v0 + 8;

    float acc[16][4];
#pragma unroll
    for (int nt = 0; nt < 16; ++nt) {
        acc[nt][0] = 0.f; acc[nt][1] = 0.f; acc[nt][2] = 0.f; acc[nt][3] = 0.f;
    }

#pragma unroll 1
    for (int o = 0; o < 27; ++o) {
        // neighbor lookups for this offset
        bool ok0 = false, ok1 = false;
        int nb0 = 0, nb1 = 0;
        if (v0 < M) {
            if (__ldg(&nbr_mask[(size_t)v0 * 27 + o]) != 0.f) { ok0 = true; nb0 = __ldg(&nbr_idx[(size_t)v0 * 27 + o]); }
        }
        if (v1 < M) {
            if (__ldg(&nbr_mask[(size_t)v1 * 27 + o]) != 0.f) { ok1 = true; nb1 = __ldg(&nbr_idx[(size_t)v1 * 27 + o]); }
        }
        int anyw = __any_sync(0xffffffffu, ok0 || ok1);
        if (lane == 0) shFlag[wid] = anyw;
        __syncthreads();   // also protects shW reuse from previous offset's compute
        int blockany = 0;
#pragma unroll
        for (int w = 0; w < 16; ++w) blockany |= shFlag[w];
        if (blockany) {
            const uint4* src = wfrag + o * 4096;
            for (int i = tid; i < 4096; i += 512) shW[i] = __ldg(&src[i]);
        }
        __syncthreads();
        if (!anyw) continue;

        const unsigned int* p0 = xp + ((size_t)nb0 << 7);
        const unsigned int* p1 = xp + ((size_t)nb1 << 7);
        const uint2 z2 = make_uint2(0u, 0u);
#pragma unroll 1
        for (int ks = 0; ks < 8; ++ks) {
            int k0 = ks * 16 + col0;
            uint2 r0a = ok0 ? *(const uint2*)(p0 + k0)     : z2;
            uint2 r0b = ok0 ? *(const uint2*)(p0 + k0 + 8) : z2;
            uint2 r1a = ok1 ? *(const uint2*)(p1 + k0)     : z2;
            uint2 r1b = ok1 ? *(const uint2*)(p1 + k0 + 8) : z2;
            uint32_t a0h = __byte_perm(r0a.x, r0a.y, 0x7632);
            uint32_t a1h = __byte_perm(r1a.x, r1a.y, 0x7632);
            uint32_t a2h = __byte_perm(r0b.x, r0b.y, 0x7632);
            uint32_t a3h = __byte_perm(r1b.x, r1b.y, 0x7632);
            uint32_t a0l = __byte_perm(r0a.x, r0a.y, 0x5410);
            uint32_t a1l = __byte_perm(r1a.x, r1a.y, 0x5410);
            uint32_t a2l = __byte_perm(r0b.x, r0b.y, 0x5410);
            uint32_t a3l = __byte_perm(r1b.x, r1b.y, 0x5410);
            const uint4* wrow = shW + (ks * 16) * 32 + lane;
#pragma unroll
            for (int nt = 0; nt < 16; ++nt) {
                uint4 wb = wrow[nt * 32];
                mma_bf16(acc[nt], a0h, a1h, a2h, a3h, wb.x, wb.y);
                mma_bf16(acc[nt], a0h, a1h, a2h, a3h, wb.z, wb.w);
                mma_bf16(acc[nt], a0l, a1l, a2l, a3l, wb.x, wb.y);
            }
        }
    }
    // store: rows v0 (c0,c1) and v1 (c2,c3), cols nt*8+col0
#pragma unroll
    for (int nt = 0; nt < 16; ++nt) {
        if (v0 < M) {
            float2 s0 = make_float2(acc[nt][0], acc[nt][1]);
            *(float2*)(y + ((size_t)v0 << 7) + nt * 8 + col0) = s0;
        }
        if (v1 < M) {
            float2 s1 = make_float2(acc[nt][2], acc[nt][3]);
            *(float2*)(y + ((size_t)v1 << 7) + nt * 8 + col0) = s1;
        }
    }
}

// ---------------- BN ----------------
__global__ __launch_bounds__(128) void bnstats_kernel(
    const float* __restrict__ y, float* __restrict__ stats, int M)
{
    int c = threadIdx.x;
    float s = 0.f, s2 = 0.f;
    for (int r = blockIdx.x; r < M; r += gridDim.x) {
        float v = y[(size_t)r * C + c];
        s += v; s2 += v * v;
    }
    atomicAdd(&stats[c], s);
    atomicAdd(&stats[C + c], s2);
}

__global__ void bnfinalize_kernel(
    const float* __restrict__ stats, const float* __restrict__ g,
    const float* __restrict__ b, float* __restrict__ ss, int M)
{
    int c = threadIdx.x;
    if (c < C) {
        float invM = 1.f / (float)M;
        float mean = stats[c] * invM;
        float var = stats[C + c] * invM - mean * mean;
        float sc = g[c] * rsqrtf(var + EPSF);
        ss[c] = sc;
        ss[C + c] = b[c] - mean * sc;
    }
}

// out = relu(y*scale + shift [+ resid]); writes packed (+ optional fp32)
__global__ void bnapply_kernel(
    const float* __restrict__ yin, const float* __restrict__ ss,
    const float* __restrict__ resid, float* __restrict__ outf,
    unsigned int* __restrict__ outp, int total)
{
    int stride = gridDim.x * blockDim.x;
    for (int i = blockIdx.x * blockDim.x + threadIdx.x; i < total; i += stride) {
        int c = i & (C - 1);
        float v = fmaf(yin[i], ss[c], ss[C + c]);
        if (resid) v += resid[i];
        v = fmaxf(v, 0.f);
        if (outf) outf[i] = v;
        outp[i] = packhl(v);
    }
}

// ---------------- head ----------------
__global__ __launch_bounds__(256) void head_kernel(
    const float* __restrict__ x, const int* __restrict__ inv,
    const float* __restrict__ gp, const float* __restrict__ w1,
    const float* __restrict__ b1, const float* __restrict__ w2,
    const float* __restrict__ b2, float* __restrict__ out, int N)
{
    __shared__ __align__(16) float shW1[C * 64];
    __shared__ __align__(16) float shW2[64 * 14];
    __shared__ __align__(16) float shB1[64];
    __shared__ __align__(16) float shB2[16];
    __shared__ __align__(16) float shPF[8][C];
    __shared__ __align__(16) float shH[8][64];
    for (int i = threadIdx.x; i < C * 64; i += 256) shW1[i] = w1[i];
    for (int i = threadIdx.x; i < 64 * 14; i += 256) shW2[i] = w2[i];
    if (threadIdx.x < 64) shB1[threadIdx.x] = b1[threadIdx.x];
    if (threadIdx.x < 14) shB2[threadIdx.x] = b2[threadIdx.x];
    __syncthreads();
    const int lane = threadIdx.x & 31;
    const int w = threadIdx.x >> 5;
    const int gw = (blockIdx.x * 256 + threadIdx.x) >> 5;
    const int nw = gridDim.x * 8;
    for (int p = gw; p < N; p += nw) {
        int v = inv[p];
        ((float4*)shPF[w])[lane] = ((const float4*)(x + (size_t)v * C))[lane];
        __syncwarp();
        float h0 = shB1[lane], h1 = shB1[lane + 32];
#pragma unroll 8
        for (int k = 0; k < C; ++k) {
            float a = shPF[w][k];
            h0 = fmaf(a, shW1[k * 64 + lane], h0);
            h1 = fmaf(a, shW1[k * 64 + lane + 32], h1);
        }
        h0 = fmaxf(h0, 0.f); h1 = fmaxf(h1, 0.f);
        shH[w][lane] = h0; shH[w][lane + 32] = h1;
        __syncwarp();
        if (lane < 14) {
            float d = shB2[lane];
#pragma unroll
            for (int j = 0; j < 64; ++j) d = fmaf(shH[w][j], shW2[j * 14 + lane], d);
            out[p * 14 + lane] = gp[p * 14 + lane] + d;
        }
        __syncwarp();
    }
}

// ---------------- launch ----------------
extern "C" void kernel_launch(void* const* d_in, const int* in_sizes, int n_in,
                              void* d_out, int out_size)
{
    const float* gp       = (const float*)d_in[0];
    const float* w_enc    = (const float*)d_in[1];
    const float* b_enc    = (const float*)d_in[2];
    const float* ln_g     = (const float*)d_in[3];
    const float* ln_b     = (const float*)d_in[4];
    const float* conv_w   = (const float*)d_in[5];
    const float* bn_g     = (const float*)d_in[6];
    const float* bn_b     = (const float*)d_in[7];
    const float* w1       = (const float*)d_in[8];
    const float* b1       = (const float*)d_in[9];
    const float* w2       = (const float*)d_in[10];
    const float* b2       = (const float*)d_in[11];
    const float* nbr_mask = (const float*)d_in[12];
    const int*   inv_idx  = (const int*)d_in[13];
    const int*   nbr_idx  = (const int*)d_in[14];
    float* out = (float*)d_out;

    const int N = in_sizes[0] / 14;
    const int M = in_sizes[12] / 27;

    float *px, *py, *pcnt, *pstats, *pss;
    unsigned int *pp, *pwf;
    cudaGetSymbolAddress((void**)&px,     g_x);
    cudaGetSymbolAddress((void**)&py,     g_y);
    cudaGetSymbolAddress((void**)&pp,     g_p);
    cudaGetSymbolAddress((void**)&pwf,    g_wfrag);
    cudaGetSymbolAddress((void**)&pcnt,   g_cnt);
    cudaGetSymbolAddress((void**)&pstats, g_stats);
    cudaGetSymbolAddress((void**)&pss,    g_ss);

    cudaFuncSetAttribute(conv_mma_kernel, cudaFuncAttributeMaxDynamicSharedMemorySize, CONV_SMEM);

    // weights -> per-lane HMMA fragments (hi/lo)
    wfrag_kernel<<<1728, 256>>>(conv_w, (uint4*)pwf, 4 * 110592);

    // encoder + scatter mean + pack
    zero_kernel<<<1184, 256>>>(px, pcnt, M);
    encoder_kernel<<<1024, 256>>>(gp, w_enc, b_enc, ln_g, ln_b, inv_idx, px, pcnt, N);
    divide_pack_kernel<<<1184, 256>>>(px, pcnt, pp, M * C);

    const int convGrid = (M + 255) / 256;
    const uint4* wf = (const uint4*)pwf;
    // stage 0
    conv_mma_kernel<<<convGrid, 512, CONV_SMEM>>>(pp, py, wf + 0 * 110592, nbr_idx, nbr_mask, M);
    zero_stats_kernel<<<1, 256>>>(pstats);
    bnstats_kernel<<<1024, 128>>>(py, pstats, M);
    bnfinalize_kernel<<<1, 128>>>(pstats, bn_g + 0 * C, bn_b + 0 * C, pss, M);
    bnapply_kernel<<<1184, 256>>>(py, pss, nullptr, nullptr, pp, M * C);
    // stage 1 (+ residual x)
    conv_mma_kernel<<<convGrid, 512, CONV_SMEM>>>(pp, py, wf + 1 * 110592, nbr_idx, nbr_mask, M);
    zero_stats_kernel<<<1, 256>>>(pstats);
    bnstats_kernel<<<1024, 128>>>(py, pstats, M);
    bnfinalize_kernel<<<1, 128>>>(pstats, bn_g + 1 * C, bn_b + 1 * C, pss, M);
    bnapply_kernel<<<1184, 256>>>(py, pss, px, px, pp, M * C);
    // stage 2
    conv_mma_kernel<<<convGrid, 512, CONV_SMEM>>>(pp, py, wf + 2 * 110592, nbr_idx, nbr_mask, M);
    zero_stats_kernel<<<1, 256>>>(pstats);
    bnstats_kernel<<<1024, 128>>>(py, pstats, M);
    bnfinalize_kernel<<<1, 128>>>(pstats, bn_g + 2 * C, bn_b + 2 * C, pss, M);
    bnapply_kernel<<<1184, 256>>>(py, pss, nullptr, nullptr, pp, M * C);
    // stage 3 (+ residual x)
    conv_mma_kernel<<<convGrid, 512, CONV_SMEM>>>(pp, py, wf + 3 * 110592, nbr_idx, nbr_mask, M);
    zero_stats_kernel<<<1, 256>>>(pstats);
    bnstats_kernel<<<1024, 128>>>(py, pstats, M);
    bnfinalize_kernel<<<1, 128>>>(pstats, bn_g + 3 * C, bn_b + 3 * C, pss, M);
    bnapply_kernel<<<1184, 256>>>(py, pss, px, px, pp, M * C);

    // head
    head_kernel<<<1024, 256>>>(px, inv_idx, gp, w1, b1, w2, b2, out, N);
}